// round 10
// baseline (speedup 1.0000x reference)
#include <cuda_runtime.h>
#include <cuda_bf16.h>
#include <mma.h>
#include <stdint.h>

using namespace nvcuda;

// ---------------- problem constants (shapes fixed by the dataset) -----------
#define MAXN 100000
#define MAXE 1600000
#define IN_C 128
#define HID_C 128
#define OUT_C 64
#define SCAN_BT 1024
#define PADR 128   // row padding so unguarded tile stores stay in-bounds

// ---------------- device scratch (no allocs; referenced directly) -----------
__device__ __align__(16) float g_deg [MAXN];
__device__ __align__(16) float g_dinv[MAXN];
__device__ __align__(16) int   g_cnt [MAXN];
__device__ __align__(16) int   g_cur [MAXN];
__device__ __align__(16) int   g_off [MAXN + 1];
__device__ __align__(16) int   g_bsum[128];
__device__ __align__(16) int2  g_csr [MAXE];          // (src, w-as-bits)
__device__ __align__(16) float g_h1[(size_t)(MAXN + PADR) * HID_C];
__device__ __align__(16) float g_a1[(size_t)MAXN * HID_C];
__device__ __align__(16) float g_h2[(size_t)(MAXN + PADR) * OUT_C];
__device__ __align__(16) float g_z [(size_t)MAXN * OUT_C];

__device__ __forceinline__ float to_tf32(float x) {
    float r;
    asm("cvt.rna.tf32.f32 %0, %1;" : "=f"(r) : "f"(x));
    return r;
}

// ---------------- degree + in-edge counting ---------------------------------
__global__ void init_kernel(int n) {
    int i = blockIdx.x * blockDim.x + threadIdx.x;
    if (i < n) { g_deg[i] = 1.0f; g_cnt[i] = 0; }
}

__global__ void deg_cnt_kernel(const int* __restrict__ dst,
                               const float* __restrict__ ew, int ne) {
    int e = blockIdx.x * blockDim.x + threadIdx.x;
    if (e < ne) {
        int d = dst[e];
        atomicAdd(&g_deg[d], ew[e]);
        atomicAdd(&g_cnt[d], 1);
    }
}

__global__ void dinv_kernel(int n) {
    int i = blockIdx.x * blockDim.x + threadIdx.x;
    if (i < n) {
        float d = g_deg[i];
        g_dinv[i] = (d > 0.0f) ? rsqrtf(d) : 0.0f;
    }
}

// ---------------- two-level coalesced scan of g_cnt -> g_off ----------------
__global__ void scan1_kernel(int n) {
    __shared__ int wsum[32];
    int tid = threadIdx.x;
    int i = blockIdx.x * SCAN_BT + tid;
    int v = (i < n) ? g_cnt[i] : 0;
    int s = v;
#pragma unroll
    for (int o = 16; o > 0; o >>= 1) s += __shfl_down_sync(0xffffffffu, s, o);
    if ((tid & 31) == 0) wsum[tid >> 5] = s;
    __syncthreads();
    if (tid < 32) {
        int t = wsum[tid];
#pragma unroll
        for (int o = 16; o > 0; o >>= 1) t += __shfl_down_sync(0xffffffffu, t, o);
        if (tid == 0) g_bsum[blockIdx.x] = t;
    }
}

__global__ void scan2_kernel(int nb) {
    __shared__ int sh[128];
    int tid = threadIdx.x;
    int v = (tid < nb) ? g_bsum[tid] : 0;
    sh[tid] = v;
    __syncthreads();
#pragma unroll
    for (int o = 1; o < 128; o <<= 1) {
        int y = 0;
        if (tid >= o) y = sh[tid - o];
        __syncthreads();
        if (tid >= o) sh[tid] += y;
        __syncthreads();
    }
    if (tid < nb) g_bsum[tid] = sh[tid] - v;   // exclusive
}

__global__ void scan3_kernel(int n) {
    __shared__ int wpre[32];
    int tid = threadIdx.x;
    int lane = tid & 31;
    int wid = tid >> 5;
    int i = blockIdx.x * SCAN_BT + tid;
    int v = (i < n) ? g_cnt[i] : 0;
    int x = v;
#pragma unroll
    for (int o = 1; o < 32; o <<= 1) {
        int y = __shfl_up_sync(0xffffffffu, x, o);
        if (lane >= o) x += y;
    }
    if (lane == 31) wpre[wid] = x;
    __syncthreads();
    if (wid == 0) {
        int t = wpre[lane];
        int tv = t;
#pragma unroll
        for (int o = 1; o < 32; o <<= 1) {
            int y = __shfl_up_sync(0xffffffffu, tv, o);
            if (lane >= o) tv += y;
        }
        wpre[lane] = tv - t;
    }
    __syncthreads();
    int bpre = g_bsum[blockIdx.x];
    int excl = bpre + wpre[wid] + (x - v);
    if (i < n) {
        g_off[i] = excl;
        g_cur[i] = excl;
        if (i == n - 1) g_off[n] = excl + v;
    }
}

// fill CSR: (src, w) pairs grouped by dst
__global__ void fill_kernel(const int* __restrict__ src,
                            const int* __restrict__ dst,
                            const float* __restrict__ ew, int ne) {
    int e = blockIdx.x * blockDim.x + threadIdx.x;
    if (e >= ne) return;
    int s = src[e];
    int d = dst[e];
    int slot = atomicAdd(&g_cur[d], 1);
    float w = g_dinv[s] * ew[e] * g_dinv[d];
    g_csr[slot] = make_int2(s, __float_as_int(w));
}

// ---------------- split-TF32 tensor-core GEMM, 128-row tiles, 8 warps -------
// C[nrows, NOUT] = A[nrows,128] @ W[128,NOUT], fp32-accurate via 3-term split.
// LAYER 1: A = X (arg), C = g_h1.   LAYER 2: A = relu(g_a1+b1), C = g_h2.
// Warp grid 4x2: warp owns 32 rows x NOUT/2 cols.
template<int NOUT, int LAYER>
__global__ void gemm_tc_kernel(const float* __restrict__ X,
                               const float* __restrict__ W,
                               const float* __restrict__ bias_in,
                               int nrows) {
    const float* __restrict__ A = (LAYER == 1) ? X : (const float*)g_a1;
    float* __restrict__ C = (LAYER == 1) ? g_h1 : g_h2;

    constexpr int KC  = 16;
    constexpr int ALD = KC + 8;              // 24
    constexpr int BLD = NOUT + 8;            // 136 / 72
    constexpr int NF  = NOUT / 32;           // col frags per warp (4 or 2)

    __shared__ __align__(16) float Ah[128 * ALD];
    __shared__ __align__(16) float Al[128 * ALD];
    __shared__ __align__(16) float Bh[KC * BLD];
    __shared__ __align__(16) float Bl[KC * BLD];

    int tid = threadIdx.x;
    int w   = tid >> 5;
    int wm  = w >> 1;                        // 0..3 row group (32 rows)
    int wn  = w & 1;                         // 0..1 col group (NOUT/2 cols)
    int row0 = blockIdx.x * 128;

    wmma::fragment<wmma::accumulator, 16, 16, 8, float> acc[2][NF];
#pragma unroll
    for (int i = 0; i < 2; i++)
#pragma unroll
        for (int j = 0; j < NF; j++) wmma::fill_fragment(acc[i][j], 0.0f);

    for (int k0 = 0; k0 < 128; k0 += KC) {
        // A chunk: 128 rows x 16 cols = 512 float4, 2 per thread
#pragma unroll
        for (int i = 0; i < 2; i++) {
            int idx = tid + i * 256;         // 0..511
            int r  = idx >> 2;
            int c4 = (idx & 3) * 4;
            float4 v = make_float4(0.f, 0.f, 0.f, 0.f);
            int row = row0 + r;
            if (row < nrows) {
                v = *(const float4*)(A + (size_t)row * 128 + k0 + c4);
                if (LAYER == 2) {
                    float4 b = *(const float4*)(bias_in + k0 + c4);
                    v.x = fmaxf(v.x + b.x, 0.0f);
                    v.y = fmaxf(v.y + b.y, 0.0f);
                    v.z = fmaxf(v.z + b.z, 0.0f);
                    v.w = fmaxf(v.w + b.w, 0.0f);
                }
            }
            float hx = to_tf32(v.x), hy = to_tf32(v.y), hz = to_tf32(v.z), hw = to_tf32(v.w);
            float* ah = Ah + r * ALD + c4;
            float* al = Al + r * ALD + c4;
            ah[0] = hx; ah[1] = hy; ah[2] = hz; ah[3] = hw;
            al[0] = v.x - hx; al[1] = v.y - hy; al[2] = v.z - hz; al[3] = v.w - hw;
        }
        // B chunk: 16 rows x NOUT cols
        constexpr int BV = KC * NOUT / 4 / 256;   // float4 per thread (2 or 1)
#pragma unroll
        for (int i = 0; i < BV; i++) {
            int idx = tid + i * 256;
            int r  = idx / (NOUT / 4);
            int c4 = (idx % (NOUT / 4)) * 4;
            float4 v = *(const float4*)(W + (size_t)(k0 + r) * NOUT + c4);
            float hx = to_tf32(v.x), hy = to_tf32(v.y), hz = to_tf32(v.z), hw = to_tf32(v.w);
            float* bh = Bh + r * BLD + c4;
            float* bl = Bl + r * BLD + c4;
            bh[0] = hx; bh[1] = hy; bh[2] = hz; bh[3] = hw;
            bl[0] = v.x - hx; bl[1] = v.y - hy; bl[2] = v.z - hz; bl[3] = v.w - hw;
        }
        __syncthreads();

#pragma unroll
        for (int ks = 0; ks < KC; ks += 8) {
            wmma::fragment<wmma::matrix_a, 16, 16, 8, wmma::precision::tf32, wmma::row_major> ah0, al0, ah1, al1;
            wmma::load_matrix_sync(ah0, Ah + (wm * 32 + 0)  * ALD + ks, ALD);
            wmma::load_matrix_sync(al0, Al + (wm * 32 + 0)  * ALD + ks, ALD);
            wmma::load_matrix_sync(ah1, Ah + (wm * 32 + 16) * ALD + ks, ALD);
            wmma::load_matrix_sync(al1, Al + (wm * 32 + 16) * ALD + ks, ALD);
#pragma unroll
            for (int j = 0; j < NF; j++) {
                wmma::fragment<wmma::matrix_b, 16, 16, 8, wmma::precision::tf32, wmma::row_major> bh, bl;
                int cb = wn * (NOUT / 2) + j * 16;
                wmma::load_matrix_sync(bh, Bh + ks * BLD + cb, BLD);
                wmma::load_matrix_sync(bl, Bl + ks * BLD + cb, BLD);
                wmma::mma_sync(acc[0][j], ah0, bh, acc[0][j]);
                wmma::mma_sync(acc[1][j], ah1, bh, acc[1][j]);
                wmma::mma_sync(acc[0][j], ah0, bl, acc[0][j]);
                wmma::mma_sync(acc[1][j], ah1, bl, acc[1][j]);
                wmma::mma_sync(acc[0][j], al0, bh, acc[0][j]);
                wmma::mma_sync(acc[1][j], al1, bh, acc[1][j]);
            }
        }
        __syncthreads();
    }

    // epilogue: direct global stores (C padded by PADR rows; tail rows are zeros)
#pragma unroll
    for (int i = 0; i < 2; i++)
#pragma unroll
        for (int j = 0; j < NF; j++) {
            int row = row0 + wm * 32 + i * 16;
            int col = wn * (NOUT / 2) + j * 16;
            wmma::store_matrix_sync(C + (size_t)row * NOUT + col, acc[i][j],
                                    NOUT, wmma::mem_row_major);
        }
}

// ---------------- CSR gather aggregation: warp per dst node ------------------
// Out[n] = H[n]*dinv[n]^2 + sum_{in-edges e} w_e * H[src_e]
template<int FEAT, int LAYER>
__global__ void gather_kernel(int n) {
    const float* __restrict__ H = (LAYER == 1) ? g_h1 : g_h2;
    float* __restrict__ Out = (LAYER == 1) ? g_a1 : g_z;
    constexpr int VW = FEAT / 32;            // floats per lane (4 or 2)

    int t = blockIdx.x * blockDim.x + threadIdx.x;
    int node = t >> 5;
    int lane = t & 31;
    if (node >= n) return;

    float di = g_dinv[node];
    float sc = di * di;

    float acc[VW];
    {
        const float* hp = H + (size_t)node * FEAT + lane * VW;
        if constexpr (VW == 4) {
            float4 f = *(const float4*)hp;
            acc[0] = f.x * sc; acc[1] = f.y * sc; acc[2] = f.z * sc; acc[3] = f.w * sc;
        } else {
            float2 f = *(const float2*)hp;
            acc[0] = f.x * sc; acc[1] = f.y * sc;
        }
    }

    int i   = g_off[node];
    int end = g_off[node + 1];

    for (; i + 4 <= end; i += 4) {
        int2 c0 = g_csr[i];
        int2 c1 = g_csr[i + 1];
        int2 c2 = g_csr[i + 2];
        int2 c3 = g_csr[i + 3];
        const float* p0 = H + (size_t)c0.x * FEAT + lane * VW;
        const float* p1 = H + (size_t)c1.x * FEAT + lane * VW;
        const float* p2 = H + (size_t)c2.x * FEAT + lane * VW;
        const float* p3 = H + (size_t)c3.x * FEAT + lane * VW;
        float w0 = __int_as_float(c0.y), w1 = __int_as_float(c1.y);
        float w2 = __int_as_float(c2.y), w3 = __int_as_float(c3.y);
        if constexpr (VW == 4) {
            float4 v0 = *(const float4*)p0;
            float4 v1 = *(const float4*)p1;
            float4 v2 = *(const float4*)p2;
            float4 v3 = *(const float4*)p3;
            acc[0] += v0.x * w0 + v1.x * w1 + v2.x * w2 + v3.x * w3;
            acc[1] += v0.y * w0 + v1.y * w1 + v2.y * w2 + v3.y * w3;
            acc[2] += v0.z * w0 + v1.z * w1 + v2.z * w2 + v3.z * w3;
            acc[3] += v0.w * w0 + v1.w * w1 + v2.w * w2 + v3.w * w3;
        } else {
            float2 v0 = *(const float2*)p0;
            float2 v1 = *(const float2*)p1;
            float2 v2 = *(const float2*)p2;
            float2 v3 = *(const float2*)p3;
            acc[0] += v0.x * w0 + v1.x * w1 + v2.x * w2 + v3.x * w3;
            acc[1] += v0.y * w0 + v1.y * w1 + v2.y * w2 + v3.y * w3;
        }
    }
    for (; i < end; i++) {
        int2 c = g_csr[i];
        float w = __int_as_float(c.y);
        const float* p = H + (size_t)c.x * FEAT + lane * VW;
        if constexpr (VW == 4) {
            float4 v = *(const float4*)p;
            acc[0] += v.x * w; acc[1] += v.y * w;
            acc[2] += v.z * w; acc[3] += v.w * w;
        } else {
            float2 v = *(const float2*)p;
            acc[0] += v.x * w; acc[1] += v.y * w;
        }
    }

    float* op = Out + (size_t)node * FEAT + lane * VW;
    if constexpr (VW == 4)
        *(float4*)op = make_float4(acc[0], acc[1], acc[2], acc[3]);
    else
        *(float2*)op = make_float2(acc[0], acc[1]);
}

// ---------------- decode: out[e] = dot(z[a]+b2, z[b]+b2) over 64 dims --------
__global__ void decode_kernel(const int* __restrict__ ea,
                              const int* __restrict__ eb,
                              const float* __restrict__ b2,
                              float* __restrict__ out, int ne) {
    long long t = (long long)blockIdx.x * blockDim.x + threadIdx.x;
    int e = (int)(t >> 5);
    int lane = (int)(t & 31);
    if (e >= ne) return;
    int a = ea[e];
    int b = eb[e];
    float2 bb = *(const float2*)(b2 + lane * 2);
    float2 va = *(const float2*)(g_z + (size_t)a * 64 + lane * 2);
    float2 vb = *(const float2*)(g_z + (size_t)b * 64 + lane * 2);
    va.x += bb.x; va.y += bb.y;
    vb.x += bb.x; vb.y += bb.y;
    float p = va.x * vb.x + va.y * vb.y;
#pragma unroll
    for (int o = 16; o > 0; o >>= 1) p += __shfl_down_sync(0xffffffffu, p, o);
    if (lane == 0) out[e] = p;
}

// ---------------- host launch ------------------------------------------------
static inline int cdiv_ll(long long a, int b) { return (int)((a + b - 1) / b); }

extern "C" void kernel_launch(void* const* d_in, const int* in_sizes, int n_in,
                              void* d_out, int out_size) {
    const float* x   = (const float*)d_in[0];
    const int*   ei  = (const int*)d_in[1];    // [2, E] int32
    const float* ew  = (const float*)d_in[2];
    const int*   eli = (const int*)d_in[3];    // [2, EL] int32
    const float* W1  = (const float*)d_in[4];
    const float* b1  = (const float*)d_in[5];
    const float* W2  = (const float*)d_in[6];
    const float* b2  = (const float*)d_in[7];
    float*       out = (float*)d_out;

    const int N  = in_sizes[0] / IN_C;
    const int E  = in_sizes[1] / 2;
    const int EL = in_sizes[3] / 2;

    const int* src = ei;
    const int* dst = ei + E;
    const int* ea  = eli;
    const int* eb  = eli + EL;

    const int T = 256;
    const int nb = (N + SCAN_BT - 1) / SCAN_BT;

    static cudaStream_t s2 = nullptr;
    static cudaEvent_t evA = nullptr, evB = nullptr;
    if (s2 == nullptr) {
        cudaStreamCreateWithFlags(&s2, cudaStreamNonBlocking);
        cudaEventCreateWithFlags(&evA, cudaEventDisableTiming);
        cudaEventCreateWithFlags(&evB, cudaEventDisableTiming);
    }

    // fork: gemm1 (independent of graph structure) runs on s2
    cudaEventRecord(evA, 0);
    cudaStreamWaitEvent(s2, evA, 0);
    gemm_tc_kernel<HID_C, 1><<<cdiv_ll(N, 128), 256, 0, s2>>>(x, W1, nullptr, N);
    cudaEventRecord(evB, s2);

    // CSR build + normalization on the main (capture) stream
    init_kernel<<<cdiv_ll(N, T), T>>>(N);
    deg_cnt_kernel<<<cdiv_ll(E, T), T>>>(dst, ew, E);
    dinv_kernel<<<cdiv_ll(N, T), T>>>(N);
    scan1_kernel<<<nb, SCAN_BT>>>(N);
    scan2_kernel<<<1, 128>>>(nb);
    scan3_kernel<<<nb, SCAN_BT>>>(N);
    fill_kernel<<<cdiv_ll(E, T), T>>>(src, dst, ew, E);

    // join: gather1 needs both h1 (s2) and CSR (main)
    cudaStreamWaitEvent(0, evB, 0);
    gather_kernel<HID_C, 1><<<cdiv_ll((long long)N * 32, T), T>>>(N);

    // layer 2 + decode on main stream
    gemm_tc_kernel<OUT_C, 2><<<cdiv_ll(N, 128), 256>>>(x, W2, b1, N);
    gather_kernel<OUT_C, 2><<<cdiv_ll((long long)N * 32, T), T>>>(N);
    decode_kernel<<<cdiv_ll((long long)EL * 32, T), T>>>(ea, eb, b2, out, EL);
}

// round 12
// speedup vs baseline: 1.0924x; 1.0924x over previous
#include <cuda_runtime.h>
#include <cuda_bf16.h>
#include <stdint.h>

// ---------------- problem constants (shapes fixed by the dataset) -----------
#define MAXN 100000
#define MAXE 1600000
#define IN_C 128
#define HID_C 128
#define OUT_C 64
#define SCAN_BT 1024
#define CHUNKS 4

// ---------------- device scratch (no allocs; referenced directly) -----------
// g_deg / g_cnt rely on zero-init at module load; cleanup_kernel restores them
// to zero at the end of every call (deterministic across calls/replays).
__device__ __align__(16) float g_deg [MAXN];
__device__ __align__(16) float g_dinv[MAXN];
__device__ __align__(16) int   g_cnt [MAXN];
__device__ __align__(16) int   g_cur [MAXN];
__device__ __align__(16) int   g_off [MAXN + 1];
__device__ __align__(16) int   g_bsum[128];
__device__ __align__(16) int2  g_csr [MAXE];          // (src, w-as-bits)
__device__ __align__(16) float g_h1[(size_t)MAXN * HID_C];
__device__ __align__(16) float g_a1[(size_t)MAXN * HID_C];
__device__ __align__(16) float g_h2[(size_t)MAXN * OUT_C];
__device__ __align__(16) float g_z [(size_t)MAXN * OUT_C];

// ---------------- degree + in-edge counting (arrays pre-zeroed) -------------
__global__ void deg_cnt_kernel(const int* __restrict__ dst,
                               const float* __restrict__ ew, int ne) {
    int e = blockIdx.x * blockDim.x + threadIdx.x;
    if (e < ne) {
        int d = dst[e];
        atomicAdd(&g_deg[d], ew[e]);
        atomicAdd(&g_cnt[d], 1);
    }
}

// ---------------- scan pass A: dinv + per-block sums of cnt -----------------
__global__ void scanA_kernel(int n) {
    __shared__ int wsum[32];
    int tid = threadIdx.x;
    int i = blockIdx.x * SCAN_BT + tid;
    int v = 0;
    if (i < n) {
        v = g_cnt[i];
        g_dinv[i] = rsqrtf(g_deg[i] + 1.0f);   // +1 = self-loop weight
    }
    int s = v;
#pragma unroll
    for (int o = 16; o > 0; o >>= 1) s += __shfl_down_sync(0xffffffffu, s, o);
    if ((tid & 31) == 0) wsum[tid >> 5] = s;
    __syncthreads();
    if (tid < 32) {
        int t = wsum[tid];
#pragma unroll
        for (int o = 16; o > 0; o >>= 1) t += __shfl_down_sync(0xffffffffu, t, o);
        if (tid == 0) g_bsum[blockIdx.x] = t;
    }
}

// ---------------- scan pass B: full exclusive scan -> g_off, g_cur ----------
// Each block redundantly scans the <=128 block sums, then scans its own span.
__global__ void scanB_kernel(int n, int nb) {
    __shared__ int bsh[128];
    __shared__ int wpre[32];
    int tid = threadIdx.x;
    int lane = tid & 31;
    int wid = tid >> 5;

    if (tid < 128) bsh[tid] = (tid < nb) ? g_bsum[tid] : 0;
    __syncthreads();
#pragma unroll
    for (int o = 1; o < 128; o <<= 1) {
        int y = 0;
        if (tid >= o && tid < 128) y = bsh[tid - o];
        __syncthreads();
        if (tid >= o && tid < 128) bsh[tid] += y;
        __syncthreads();
    }
    int bpre = bsh[blockIdx.x] - g_bsum[blockIdx.x];   // exclusive block prefix

    int i = blockIdx.x * SCAN_BT + tid;
    int v = (i < n) ? g_cnt[i] : 0;
    int x = v;
#pragma unroll
    for (int o = 1; o < 32; o <<= 1) {
        int y = __shfl_up_sync(0xffffffffu, x, o);
        if (lane >= o) x += y;
    }
    if (lane == 31) wpre[wid] = x;
    __syncthreads();
    if (wid == 0) {
        int t = wpre[lane];
        int tv = t;
#pragma unroll
        for (int o = 1; o < 32; o <<= 1) {
            int y = __shfl_up_sync(0xffffffffu, tv, o);
            if (lane >= o) tv += y;
        }
        wpre[lane] = tv - t;
    }
    __syncthreads();
    int excl = bpre + wpre[wid] + (x - v);
    if (i < n) {
        g_off[i] = excl;
        g_cur[i] = excl;
        if (i == n - 1) g_off[n] = excl + v;
    }
}

// fill CSR: (src, w) pairs grouped by dst
__global__ void fill_kernel(const int* __restrict__ src,
                            const int* __restrict__ dst,
                            const float* __restrict__ ew, int ne) {
    int e = blockIdx.x * blockDim.x + threadIdx.x;
    if (e >= ne) return;
    int s = src[e];
    int d = dst[e];
    int slot = atomicAdd(&g_cur[d], 1);
    float w = g_dinv[s] * ew[e] * g_dinv[d];
    g_csr[slot] = make_int2(s, __float_as_int(w));
}

// restore scratch counters to zero for the next call (determinism)
__global__ void cleanup_kernel(int n) {
    int i = blockIdx.x * blockDim.x + threadIdx.x;
    if (i < n) { g_deg[i] = 0.0f; g_cnt[i] = 0; }
}

// ---------------- tiled FP32 GEMM (row-range chunked) ------------------------
// LAYER 1: A = X (arg),         C = g_h1
// LAYER 2: A = relu(g_a1 + b1), C = g_h2
template<int NOUT, int LAYER>
__global__ void gemm_kernel(const float* __restrict__ X,
                            const float* __restrict__ W,
                            const float* __restrict__ bias_in,
                            int rbase, int nrows) {
    const float* __restrict__ A = (LAYER == 1) ? X : (const float*)g_a1;
    float* __restrict__ C = (LAYER == 1) ? g_h1 : g_h2;

    constexpr int CPT = NOUT / 16;
    __shared__ float As[64][33];
    __shared__ float Ws[32 * NOUT];

    int tid = threadIdx.x;
    int tx = tid & 15, ty = tid >> 4;
    int row0 = rbase + blockIdx.x * 64;

    float acc[4][CPT];
#pragma unroll
    for (int i = 0; i < 4; i++)
#pragma unroll
        for (int j = 0; j < CPT; j++) acc[i][j] = 0.0f;

    for (int k0 = 0; k0 < 128; k0 += 32) {
#pragma unroll
        for (int i = 0; i < 2; i++) {
            int idx = tid + i * 256;
            int r  = idx >> 3;
            int cs = (idx & 7) * 4;
            float4 v = make_float4(0.f, 0.f, 0.f, 0.f);
            int row = row0 + r;
            if (row < nrows) {
                v = *(const float4*)(A + (size_t)row * 128 + k0 + cs);
                if (LAYER == 2) {
                    float4 b = *(const float4*)(bias_in + k0 + cs);
                    v.x = fmaxf(v.x + b.x, 0.0f);
                    v.y = fmaxf(v.y + b.y, 0.0f);
                    v.z = fmaxf(v.z + b.z, 0.0f);
                    v.w = fmaxf(v.w + b.w, 0.0f);
                }
            }
            As[r][cs + 0] = v.x; As[r][cs + 1] = v.y;
            As[r][cs + 2] = v.z; As[r][cs + 3] = v.w;
        }
        constexpr int WV = (32 * NOUT) / 4 / 256;
        const float4* Wg = (const float4*)(W + k0 * NOUT);
        float4* Wsv = (float4*)Ws;
#pragma unroll
        for (int i = 0; i < WV; i++) Wsv[tid + i * 256] = Wg[tid + i * 256];
        __syncthreads();

#pragma unroll
        for (int k = 0; k < 32; k++) {
            float a0 = As[ty * 4 + 0][k];
            float a1v = As[ty * 4 + 1][k];
            float a2 = As[ty * 4 + 2][k];
            float a3 = As[ty * 4 + 3][k];
            const float* wrow = &Ws[k * NOUT + tx * CPT];
#pragma unroll
            for (int j = 0; j < CPT; j++) {
                float b = wrow[j];
                acc[0][j] += a0 * b;
                acc[1][j] += a1v * b;
                acc[2][j] += a2 * b;
                acc[3][j] += a3 * b;
            }
        }
        __syncthreads();
    }

#pragma unroll
    for (int i = 0; i < 4; i++) {
        int row = row0 + ty * 4 + i;
        if (row < nrows) {
            float* cp = C + (size_t)row * NOUT + tx * CPT;
#pragma unroll
            for (int j = 0; j < CPT; j += 4)
                *(float4*)(cp + j) = make_float4(acc[i][j], acc[i][j + 1],
                                                 acc[i][j + 2], acc[i][j + 3]);
        }
    }
}

// ---------------- CSR gather aggregation: warp per dst node (node range) -----
// Out[n] = H[n]*dinv[n]^2 + sum_{in-edges e} w_e * H[src_e]
template<int FEAT, int LAYER>
__global__ void gather_kernel(int nbase, int nend) {
    const float* __restrict__ H = (LAYER == 1) ? g_h1 : g_h2;
    float* __restrict__ Out = (LAYER == 1) ? g_a1 : g_z;
    constexpr int VW = FEAT / 32;            // floats per lane (4 or 2)

    int t = blockIdx.x * blockDim.x + threadIdx.x;
    int node = nbase + (t >> 5);
    int lane = t & 31;
    if (node >= nend) return;

    float di = g_dinv[node];
    float sc = di * di;

    float acc[VW];
    {
        const float* hp = H + (size_t)node * FEAT + lane * VW;
        if constexpr (VW == 4) {
            float4 f = *(const float4*)hp;
            acc[0] = f.x * sc; acc[1] = f.y * sc; acc[2] = f.z * sc; acc[3] = f.w * sc;
        } else {
            float2 f = *(const float2*)hp;
            acc[0] = f.x * sc; acc[1] = f.y * sc;
        }
    }

    int i   = g_off[node];
    int end = g_off[node + 1];

    for (; i + 4 <= end; i += 4) {
        int2 c0 = g_csr[i];
        int2 c1 = g_csr[i + 1];
        int2 c2 = g_csr[i + 2];
        int2 c3 = g_csr[i + 3];
        const float* p0 = H + (size_t)c0.x * FEAT + lane * VW;
        const float* p1 = H + (size_t)c1.x * FEAT + lane * VW;
        const float* p2 = H + (size_t)c2.x * FEAT + lane * VW;
        const float* p3 = H + (size_t)c3.x * FEAT + lane * VW;
        float w0 = __int_as_float(c0.y), w1 = __int_as_float(c1.y);
        float w2 = __int_as_float(c2.y), w3 = __int_as_float(c3.y);
        if constexpr (VW == 4) {
            float4 v0 = *(const float4*)p0;
            float4 v1 = *(const float4*)p1;
            float4 v2 = *(const float4*)p2;
            float4 v3 = *(const float4*)p3;
            acc[0] += v0.x * w0 + v1.x * w1 + v2.x * w2 + v3.x * w3;
            acc[1] += v0.y * w0 + v1.y * w1 + v2.y * w2 + v3.y * w3;
            acc[2] += v0.z * w0 + v1.z * w1 + v2.z * w2 + v3.z * w3;
            acc[3] += v0.w * w0 + v1.w * w1 + v2.w * w2 + v3.w * w3;
        } else {
            float2 v0 = *(const float2*)p0;
            float2 v1 = *(const float2*)p1;
            float2 v2 = *(const float2*)p2;
            float2 v3 = *(const float2*)p3;
            acc[0] += v0.x * w0 + v1.x * w1 + v2.x * w2 + v3.x * w3;
            acc[1] += v0.y * w0 + v1.y * w1 + v2.y * w2 + v3.y * w3;
        }
    }
    for (; i < end; i++) {
        int2 c = g_csr[i];
        float w = __int_as_float(c.y);
        const float* p = H + (size_t)c.x * FEAT + lane * VW;
        if constexpr (VW == 4) {
            float4 v = *(const float4*)p;
            acc[0] += v.x * w; acc[1] += v.y * w;
            acc[2] += v.z * w; acc[3] += v.w * w;
        } else {
            float2 v = *(const float2*)p;
            acc[0] += v.x * w; acc[1] += v.y * w;
        }
    }

    float* op = Out + (size_t)node * FEAT + lane * VW;
    if constexpr (VW == 4)
        *(float4*)op = make_float4(acc[0], acc[1], acc[2], acc[3]);
    else
        *(float2*)op = make_float2(acc[0], acc[1]);
}

// ---------------- decode: out[e] = dot(z[a]+b2, z[b]+b2) over 64 dims --------
__global__ void decode_kernel(const int* __restrict__ ea,
                              const int* __restrict__ eb,
                              const float* __restrict__ b2,
                              float* __restrict__ out, int ne) {
    long long t = (long long)blockIdx.x * blockDim.x + threadIdx.x;
    int e = (int)(t >> 5);
    int lane = (int)(t & 31);
    if (e >= ne) return;
    int a = ea[e];
    int b = eb[e];
    float2 bb = *(const float2*)(b2 + lane * 2);
    float2 va = *(const float2*)(g_z + (size_t)a * 64 + lane * 2);
    float2 vb = *(const float2*)(g_z + (size_t)b * 64 + lane * 2);
    va.x += bb.x; va.y += bb.y;
    vb.x += bb.x; vb.y += bb.y;
    float p = va.x * vb.x + va.y * vb.y;
#pragma unroll
    for (int o = 16; o > 0; o >>= 1) p += __shfl_down_sync(0xffffffffu, p, o);
    if (lane == 0) out[e] = p;
}

// ---------------- host launch ------------------------------------------------
static inline int cdiv_ll(long long a, int b) { return (int)((a + b - 1) / b); }

extern "C" void kernel_launch(void* const* d_in, const int* in_sizes, int n_in,
                              void* d_out, int out_size) {
    const float* x   = (const float*)d_in[0];
    const int*   ei  = (const int*)d_in[1];    // [2, E] int32
    const float* ew  = (const float*)d_in[2];
    const int*   eli = (const int*)d_in[3];    // [2, EL] int32
    const float* W1  = (const float*)d_in[4];
    const float* b1  = (const float*)d_in[5];
    const float* W2  = (const float*)d_in[6];
    const float* b2  = (const float*)d_in[7];
    float*       out = (float*)d_out;

    const int N  = in_sizes[0] / IN_C;
    const int E  = in_sizes[1] / 2;
    const int EL = in_sizes[3] / 2;

    const int* src = ei;
    const int* dst = ei + E;
    const int* ea  = eli;
    const int* eb  = eli + EL;

    const int T = 256;
    const int nb = (N + SCAN_BT - 1) / SCAN_BT;

    // chunk boundaries (64-aligned) for gather1/gemm2 pipelining
    int step = (((N + CHUNKS - 1) / CHUNKS) + 63) / 64 * 64;
    int cb[CHUNKS + 1];
    for (int c = 0; c <= CHUNKS; c++) {
        long long v = (long long)c * step;
        cb[c] = (v > N) ? N : (int)v;
    }

    static cudaStream_t s2 = nullptr;
    static cudaEvent_t evA = nullptr, evB = nullptr, evM = nullptr;
    static cudaEvent_t evG[CHUNKS] = {};
    if (s2 == nullptr) {
        cudaStreamCreateWithFlags(&s2, cudaStreamNonBlocking);
        cudaEventCreateWithFlags(&evA, cudaEventDisableTiming);
        cudaEventCreateWithFlags(&evB, cudaEventDisableTiming);
        cudaEventCreateWithFlags(&evM, cudaEventDisableTiming);
        for (int c = 0; c < CHUNKS; c++)
            cudaEventCreateWithFlags(&evG[c], cudaEventDisableTiming);
    }

    // fork: gemm1 (independent of graph structure) on s2
    cudaEventRecord(evA, 0);
    cudaStreamWaitEvent(s2, evA, 0);
    gemm_kernel<HID_C, 1><<<cdiv_ll(N, 64), 256, 0, s2>>>(x, W1, nullptr, 0, N);
    cudaEventRecord(evB, s2);

    // CSR build + normalization on main stream
    deg_cnt_kernel<<<cdiv_ll(E, T), T>>>(dst, ew, E);
    scanA_kernel<<<nb, SCAN_BT>>>(N);
    scanB_kernel<<<nb, SCAN_BT>>>(N, nb);
    fill_kernel<<<cdiv_ll(E, T), T>>>(src, dst, ew, E);

    // join: gather1 chunks need CSR (main order) + h1 (evB)
    cudaStreamWaitEvent(0, evB, 0);
    for (int c = 0; c < CHUNKS; c++) {
        int nn = cb[c + 1] - cb[c];
        if (nn > 0)
            gather_kernel<HID_C, 1><<<cdiv_ll((long long)nn * 32, T), T>>>(cb[c], cb[c + 1]);
        cudaEventRecord(evG[c], 0);
    }
    // gemm2 chunks pipeline on s2 behind their gather1 chunk
    for (int c = 0; c < CHUNKS; c++) {
        cudaStreamWaitEvent(s2, evG[c], 0);
        int rows = cb[c + 1] - cb[c];
        if (rows > 0)
            gemm_kernel<OUT_C, 2><<<cdiv_ll(rows, 64), 256, 0, s2>>>(x, W2, b1, cb[c], N);
    }
    cudaEventRecord(evM, s2);
    cudaStreamWaitEvent(0, evM, 0);

    // layer 2 aggregation + decode + state restore on main stream
    gather_kernel<OUT_C, 2><<<cdiv_ll((long long)N * 32, T), T>>>(0, N);
    decode_kernel<<<cdiv_ll((long long)EL * 32, T), T>>>(ea, eb, b2, out, EL);
    cleanup_kernel<<<cdiv_ll(N, T), T>>>(N);
}

// round 13
// speedup vs baseline: 1.1799x; 1.0802x over previous
#include <cuda_runtime.h>
#include <cuda_bf16.h>
#include <stdint.h>

// ---------------- problem constants (shapes fixed by the dataset) -----------
#define MAXN 100000
#define MAXE 1600000
#define IN_C 128
#define HID_C 128
#define OUT_C 64
#define SCAN_BT 1024

// ---------------- device scratch (no allocs; referenced directly) -----------
// g_deg / g_cnt are zero at module load; cleanup_kernel restores them to zero
// every call (off the critical path), keeping kernel_launch deterministic.
__device__ __align__(16) float g_deg [MAXN];
__device__ __align__(16) float g_dinv[MAXN];
__device__ __align__(16) int   g_cnt [MAXN];
__device__ __align__(16) int   g_cur [MAXN];
__device__ __align__(16) int   g_off [MAXN + 1];
__device__ __align__(16) int   g_bsum[128];
__device__ __align__(16) int2  g_csr [MAXE];          // (src, w-as-bits)
__device__ __align__(16) float g_h1[(size_t)MAXN * HID_C];
__device__ __align__(16) float g_a1[(size_t)MAXN * HID_C];
__device__ __align__(16) float g_h2[(size_t)MAXN * OUT_C];
__device__ __align__(16) float g_z [(size_t)MAXN * OUT_C];

// ---------------- degree + in-edge counting (arrays pre-zeroed) -------------
__global__ void deg_cnt_kernel(const int* __restrict__ dst,
                               const float* __restrict__ ew, int ne) {
    int e = blockIdx.x * blockDim.x + threadIdx.x;
    if (e < ne) {
        int d = dst[e];
        atomicAdd(&g_deg[d], ew[e]);
        atomicAdd(&g_cnt[d], 1);
    }
}

// ---------------- scan pass A: dinv + per-block sums of cnt -----------------
__global__ void scanA_kernel(int n) {
    __shared__ int wsum[32];
    int tid = threadIdx.x;
    int i = blockIdx.x * SCAN_BT + tid;
    int v = 0;
    if (i < n) {
        v = g_cnt[i];
        g_dinv[i] = rsqrtf(g_deg[i] + 1.0f);   // +1 = self-loop weight; deg>0 always
    }
    int s = v;
#pragma unroll
    for (int o = 16; o > 0; o >>= 1) s += __shfl_down_sync(0xffffffffu, s, o);
    if ((tid & 31) == 0) wsum[tid >> 5] = s;
    __syncthreads();
    if (tid < 32) {
        int t = wsum[tid];
#pragma unroll
        for (int o = 16; o > 0; o >>= 1) t += __shfl_down_sync(0xffffffffu, t, o);
        if (tid == 0) g_bsum[blockIdx.x] = t;
    }
}

// ---------------- scan pass B: full exclusive scan -> g_off, g_cur ----------
// Each block redundantly scans the <=128 block sums, then scans its own span.
__global__ void scanB_kernel(int n, int nb) {
    __shared__ int bsh[128];
    __shared__ int wpre[32];
    int tid = threadIdx.x;
    int lane = tid & 31;
    int wid = tid >> 5;

    if (tid < 128) bsh[tid] = (tid < nb) ? g_bsum[tid] : 0;
    __syncthreads();
#pragma unroll
    for (int o = 1; o < 128; o <<= 1) {
        int y = 0;
        if (tid >= o && tid < 128) y = bsh[tid - o];
        __syncthreads();
        if (tid >= o && tid < 128) bsh[tid] += y;
        __syncthreads();
    }
    int bpre = bsh[blockIdx.x] - g_bsum[blockIdx.x];   // exclusive block prefix

    int i = blockIdx.x * SCAN_BT + tid;
    int v = (i < n) ? g_cnt[i] : 0;
    int x = v;
#pragma unroll
    for (int o = 1; o < 32; o <<= 1) {
        int y = __shfl_up_sync(0xffffffffu, x, o);
        if (lane >= o) x += y;
    }
    if (lane == 31) wpre[wid] = x;
    __syncthreads();
    if (wid == 0) {
        int t = wpre[lane];
        int tv = t;
#pragma unroll
        for (int o = 1; o < 32; o <<= 1) {
            int y = __shfl_up_sync(0xffffffffu, tv, o);
            if (lane >= o) tv += y;
        }
        wpre[lane] = tv - t;
    }
    __syncthreads();
    int excl = bpre + wpre[wid] + (x - v);
    if (i < n) {
        g_off[i] = excl;
        g_cur[i] = excl;
        if (i == n - 1) g_off[n] = excl + v;
    }
}

// fill CSR: (src, w) pairs grouped by dst
__global__ void fill_kernel(const int* __restrict__ src,
                            const int* __restrict__ dst,
                            const float* __restrict__ ew, int ne) {
    int e = blockIdx.x * blockDim.x + threadIdx.x;
    if (e >= ne) return;
    int s = src[e];
    int d = dst[e];
    int slot = atomicAdd(&g_cur[d], 1);
    float w = g_dinv[s] * ew[e] * g_dinv[d];
    g_csr[slot] = make_int2(s, __float_as_int(w));
}

// restore scratch counters to zero for the next call (determinism)
__global__ void cleanup_kernel(int n) {
    int i = blockIdx.x * blockDim.x + threadIdx.x;
    if (i < n) { g_deg[i] = 0.0f; g_cnt[i] = 0; }
}

// ---------------- tiled FP32 GEMM -------------------------------------------
// LAYER 1: A = X (arg),         C = g_h1
// LAYER 2: A = relu(g_a1 + b1), C = g_h2
template<int NOUT, int LAYER>
__global__ void gemm_kernel(const float* __restrict__ X,
                            const float* __restrict__ W,
                            const float* __restrict__ bias_in,
                            int nrows) {
    const float* __restrict__ A = (LAYER == 1) ? X : (const float*)g_a1;
    float* __restrict__ C = (LAYER == 1) ? g_h1 : g_h2;

    constexpr int CPT = NOUT / 16;
    __shared__ float As[64][33];
    __shared__ float Ws[32 * NOUT];

    int tid = threadIdx.x;
    int tx = tid & 15, ty = tid >> 4;
    int row0 = blockIdx.x * 64;

    float acc[4][CPT];
#pragma unroll
    for (int i = 0; i < 4; i++)
#pragma unroll
        for (int j = 0; j < CPT; j++) acc[i][j] = 0.0f;

    for (int k0 = 0; k0 < 128; k0 += 32) {
#pragma unroll
        for (int i = 0; i < 2; i++) {
            int idx = tid + i * 256;
            int r  = idx >> 3;
            int cs = (idx & 7) * 4;
            float4 v = make_float4(0.f, 0.f, 0.f, 0.f);
            int row = row0 + r;
            if (row < nrows) {
                v = *(const float4*)(A + (size_t)row * 128 + k0 + cs);
                if (LAYER == 2) {
                    float4 b = *(const float4*)(bias_in + k0 + cs);
                    v.x = fmaxf(v.x + b.x, 0.0f);
                    v.y = fmaxf(v.y + b.y, 0.0f);
                    v.z = fmaxf(v.z + b.z, 0.0f);
                    v.w = fmaxf(v.w + b.w, 0.0f);
                }
            }
            As[r][cs + 0] = v.x; As[r][cs + 1] = v.y;
            As[r][cs + 2] = v.z; As[r][cs + 3] = v.w;
        }
        constexpr int WV = (32 * NOUT) / 4 / 256;
        const float4* Wg = (const float4*)(W + k0 * NOUT);
        float4* Wsv = (float4*)Ws;
#pragma unroll
        for (int i = 0; i < WV; i++) Wsv[tid + i * 256] = Wg[tid + i * 256];
        __syncthreads();

#pragma unroll
        for (int k = 0; k < 32; k++) {
            float a0 = As[ty * 4 + 0][k];
            float a1v = As[ty * 4 + 1][k];
            float a2 = As[ty * 4 + 2][k];
            float a3 = As[ty * 4 + 3][k];
            const float* wrow = &Ws[k * NOUT + tx * CPT];
#pragma unroll
            for (int j = 0; j < CPT; j++) {
                float b = wrow[j];
                acc[0][j] += a0 * b;
                acc[1][j] += a1v * b;
                acc[2][j] += a2 * b;
                acc[3][j] += a3 * b;
            }
        }
        __syncthreads();
    }

#pragma unroll
    for (int i = 0; i < 4; i++) {
        int row = row0 + ty * 4 + i;
        if (row < nrows) {
            float* cp = C + (size_t)row * NOUT + tx * CPT;
#pragma unroll
            for (int j = 0; j < CPT; j += 4)
                *(float4*)(cp + j) = make_float4(acc[i][j], acc[i][j + 1],
                                                 acc[i][j + 2], acc[i][j + 3]);
        }
    }
}

// ---------------- CSR gather aggregation: warp per dst node ------------------
// Out[n] = H[n]*dinv[n]^2 + sum_{in-edges e} w_e * H[src_e]
template<int FEAT, int LAYER>
__global__ void gather_kernel(int n) {
    const float* __restrict__ H = (LAYER == 1) ? g_h1 : g_h2;
    float* __restrict__ Out = (LAYER == 1) ? g_a1 : g_z;
    constexpr int VW = FEAT / 32;            // floats per lane (4 or 2)

    int t = blockIdx.x * blockDim.x + threadIdx.x;
    int node = t >> 5;
    int lane = t & 31;
    if (node >= n) return;

    float di = g_dinv[node];
    float sc = di * di;

    float acc[VW];
    {
        const float* hp = H + (size_t)node * FEAT + lane * VW;
        if constexpr (VW == 4) {
            float4 f = *(const float4*)hp;
            acc[0] = f.x * sc; acc[1] = f.y * sc; acc[2] = f.z * sc; acc[3] = f.w * sc;
        } else {
            float2 f = *(const float2*)hp;
            acc[0] = f.x * sc; acc[1] = f.y * sc;
        }
    }

    int i   = g_off[node];
    int end = g_off[node + 1];

    for (; i + 4 <= end; i += 4) {
        int2 c0 = g_csr[i];
        int2 c1 = g_csr[i + 1];
        int2 c2 = g_csr[i + 2];
        int2 c3 = g_csr[i + 3];
        const float* p0 = H + (size_t)c0.x * FEAT + lane * VW;
        const float* p1 = H + (size_t)c1.x * FEAT + lane * VW;
        const float* p2 = H + (size_t)c2.x * FEAT + lane * VW;
        const float* p3 = H + (size_t)c3.x * FEAT + lane * VW;
        float w0 = __int_as_float(c0.y), w1 = __int_as_float(c1.y);
        float w2 = __int_as_float(c2.y), w3 = __int_as_float(c3.y);
        if constexpr (VW == 4) {
            float4 v0 = *(const float4*)p0;
            float4 v1 = *(const float4*)p1;
            float4 v2 = *(const float4*)p2;
            float4 v3 = *(const float4*)p3;
            acc[0] += v0.x * w0 + v1.x * w1 + v2.x * w2 + v3.x * w3;
            acc[1] += v0.y * w0 + v1.y * w1 + v2.y * w2 + v3.y * w3;
            acc[2] += v0.z * w0 + v1.z * w1 + v2.z * w2 + v3.z * w3;
            acc[3] += v0.w * w0 + v1.w * w1 + v2.w * w2 + v3.w * w3;
        } else {
            float2 v0 = *(const float2*)p0;
            float2 v1 = *(const float2*)p1;
            float2 v2 = *(const float2*)p2;
            float2 v3 = *(const float2*)p3;
            acc[0] += v0.x * w0 + v1.x * w1 + v2.x * w2 + v3.x * w3;
            acc[1] += v0.y * w0 + v1.y * w1 + v2.y * w2 + v3.y * w3;
        }
    }
    for (; i < end; i++) {
        int2 c = g_csr[i];
        float w = __int_as_float(c.y);
        const float* p = H + (size_t)c.x * FEAT + lane * VW;
        if constexpr (VW == 4) {
            float4 v = *(const float4*)p;
            acc[0] += v.x * w; acc[1] += v.y * w;
            acc[2] += v.z * w; acc[3] += v.w * w;
        } else {
            float2 v = *(const float2*)p;
            acc[0] += v.x * w; acc[1] += v.y * w;
        }
    }

    float* op = Out + (size_t)node * FEAT + lane * VW;
    if constexpr (VW == 4)
        *(float4*)op = make_float4(acc[0], acc[1], acc[2], acc[3]);
    else
        *(float2*)op = make_float2(acc[0], acc[1]);
}

// ---------------- decode: out[e] = dot(z[a]+b2, z[b]+b2) over 64 dims --------
__global__ void decode_kernel(const int* __restrict__ ea,
                              const int* __restrict__ eb,
                              const float* __restrict__ b2,
                              float* __restrict__ out, int ne) {
    long long t = (long long)blockIdx.x * blockDim.x + threadIdx.x;
    int e = (int)(t >> 5);
    int lane = (int)(t & 31);
    if (e >= ne) return;
    int a = ea[e];
    int b = eb[e];
    float2 bb = *(const float2*)(b2 + lane * 2);
    float2 va = *(const float2*)(g_z + (size_t)a * 64 + lane * 2);
    float2 vb = *(const float2*)(g_z + (size_t)b * 64 + lane * 2);
    va.x += bb.x; va.y += bb.y;
    vb.x += bb.x; vb.y += bb.y;
    float p = va.x * vb.x + va.y * vb.y;
#pragma unroll
    for (int o = 16; o > 0; o >>= 1) p += __shfl_down_sync(0xffffffffu, p, o);
    if (lane == 0) out[e] = p;
}

// ---------------- host launch ------------------------------------------------
static inline int cdiv_ll(long long a, int b) { return (int)((a + b - 1) / b); }

extern "C" void kernel_launch(void* const* d_in, const int* in_sizes, int n_in,
                              void* d_out, int out_size) {
    const float* x   = (const float*)d_in[0];
    const int*   ei  = (const int*)d_in[1];    // [2, E] int32
    const float* ew  = (const float*)d_in[2];
    const int*   eli = (const int*)d_in[3];    // [2, EL] int32
    const float* W1  = (const float*)d_in[4];
    const float* b1  = (const float*)d_in[5];
    const float* W2  = (const float*)d_in[6];
    const float* b2  = (const float*)d_in[7];
    float*       out = (float*)d_out;

    const int N  = in_sizes[0] / IN_C;
    const int E  = in_sizes[1] / 2;
    const int EL = in_sizes[3] / 2;

    const int* src = ei;
    const int* dst = ei + E;
    const int* ea  = eli;
    const int* eb  = eli + EL;

    const int T = 256;
    const int nb = (N + SCAN_BT - 1) / SCAN_BT;

    static cudaStream_t s2 = nullptr;
    static cudaEvent_t evA = nullptr, evB = nullptr, evC = nullptr;
    if (s2 == nullptr) {
        cudaStreamCreateWithFlags(&s2, cudaStreamNonBlocking);
        cudaEventCreateWithFlags(&evA, cudaEventDisableTiming);
        cudaEventCreateWithFlags(&evB, cudaEventDisableTiming);
        cudaEventCreateWithFlags(&evC, cudaEventDisableTiming);
    }

    // fork: gemm1 (independent of graph structure) runs on s2
    cudaEventRecord(evA, 0);
    cudaStreamWaitEvent(s2, evA, 0);
    gemm_kernel<HID_C, 1><<<cdiv_ll(N, 64), 256, 0, s2>>>(x, W1, nullptr, N);
    cudaEventRecord(evB, s2);

    // CSR build + normalization on the main (capture) stream
    deg_cnt_kernel<<<cdiv_ll(E, T), T>>>(dst, ew, E);
    scanA_kernel<<<nb, SCAN_BT>>>(N);
    scanB_kernel<<<nb, SCAN_BT>>>(N, nb);
    fill_kernel<<<cdiv_ll(E, T), T>>>(src, dst, ew, E);

    // cleanup (deg/cnt dead after scanB; restore zeros off the critical path,
    // after gemm1 finishes on s2 so it doesn't steal SMs from it)
    cudaStreamWaitEvent(s2, evA, 0);
    cleanup_kernel<<<cdiv_ll(N, T), T, 0, s2>>>(N);
    cudaEventRecord(evC, s2);

    // join: gather1 needs both h1 (s2) and CSR (main)
    cudaStreamWaitEvent(0, evB, 0);
    gather_kernel<HID_C, 1><<<cdiv_ll((long long)N * 32, T), T>>>(N);

    // layer 2 + decode on main stream
    gemm_kernel<OUT_C, 2><<<cdiv_ll(N, 64), 256>>>(x, W2, b1, N);
    gather_kernel<OUT_C, 2><<<cdiv_ll((long long)N * 32, T), T>>>(N);
    decode_kernel<<<cdiv_ll((long long)EL * 32, T), T>>>(ea, eb, b2, out, EL);

    // make the graph's end state include cleanup
    cudaStreamWaitEvent(0, evC, 0);
}